// round 3
// baseline (speedup 1.0000x reference)
#include <cuda_runtime.h>
#include <cuda_bf16.h>

// Scratch (no cudaMalloc allowed): transform matrix, its diagonal, and a
// "matrix is diagonal" flag, computed fresh every launch by prep_kernel.
__device__ float g_ht[256];    // h_t[j][i] = hadamard[j][i] * signs[j]
__device__ float g_diag[16];
__device__ int   g_is_diag;

// One block, 256 threads: thread t handles element (j = t/16, i = t%16).
__global__ void had_prep_kernel(const float* __restrict__ hadamard,
                                const float* __restrict__ signs) {
    __shared__ int s_offdiag;
    int t = threadIdx.x;
    int j = t >> 4;
    int i = t & 15;
    if (t == 0) s_offdiag = 0;
    __syncthreads();
    float v = hadamard[t] * signs[j];
    g_ht[t] = v;
    if (i == j) g_diag[j] = v;
    if (i != j && v != 0.0f) atomicExch(&s_offdiag, 1);
    __syncthreads();
    if (t == 0) g_is_diag = (s_offdiag == 0) ? 1 : 0;
}

// Diagonal fast path: fully coalesced streaming scale.
// Each thread processes VEC float4s spaced one grid-stride apart, so adjacent
// lanes touch adjacent float4s (4 x 128B lines per warp LDG — the minimum).
// Diag factor for global float4 index g is segment (g & 3) of diag[16].
#define VEC 4
__global__ void __launch_bounds__(256)
had_diag_kernel(const float4* __restrict__ x, float4* __restrict__ out,
                long n_vec) {
    __shared__ float4 s_d[4];   // diag as 4 float4 segments
    __shared__ int s_flag;

    int t = threadIdx.x;
    if (t < 4) s_d[t] = make_float4(g_diag[t * 4 + 0], g_diag[t * 4 + 1],
                                    g_diag[t * 4 + 2], g_diag[t * 4 + 3]);
    if (t == 0) s_flag = g_is_diag;
    __syncthreads();
    if (!s_flag) return;                       // general kernel handles it

    long stride = (long)gridDim.x * 256;
    long g0 = (long)blockIdx.x * 256 + t;

    // Front-batch all VEC loads (MLP = 4).
    float4 v[VEC];
    long   gi[VEC];
    #pragma unroll
    for (int k = 0; k < VEC; ++k) {
        gi[k] = g0 + (long)k * stride;
        if (gi[k] < n_vec) v[k] = x[gi[k]];
    }
    #pragma unroll
    for (int k = 0; k < VEC; ++k) {
        if (gi[k] < n_vec) {
            float4 d = s_d[(int)(gi[k] & 3)];
            float4 r = make_float4(v[k].x * d.x, v[k].y * d.y,
                                   v[k].z * d.z, v[k].w * d.w);
            out[gi[k]] = r;
        }
    }
}

// General fallback: one thread per output float4; gathers its 16-input tile.
// Only runs when h_t is NOT diagonal (never for this dataset's inputs).
__global__ void __launch_bounds__(256)
had_general_kernel(const float4* __restrict__ x, float4* __restrict__ out,
                   long n_vec) {
    __shared__ float s_ht[256];
    __shared__ int s_flag;
    int t = threadIdx.x;
    s_ht[t] = g_ht[t];
    if (t == 0) s_flag = g_is_diag;
    __syncthreads();
    if (s_flag) return;                        // diag kernel handled it

    long g = (long)blockIdx.x * 256 + t;
    if (g >= n_vec) return;
    long tile = g >> 2;                        // 4 float4s per 16-elem tile
    int  seg  = (int)(g & 3);                  // which 4 outputs this thread makes

    const float* xt = (const float*)(x + tile * 4);
    float xv[16];
    #pragma unroll
    for (int i = 0; i < 16; ++i) xv[i] = xt[i];

    float o[4];
    #pragma unroll
    for (int jj = 0; jj < 4; ++jj) {
        int j = seg * 4 + jj;
        float acc = 0.0f;
        #pragma unroll
        for (int i = 0; i < 16; ++i)
            acc = fmaf(xv[i], s_ht[j * 16 + i], acc);
        o[jj] = acc;
    }
    out[g] = make_float4(o[0], o[1], o[2], o[3]);
}

extern "C" void kernel_launch(void* const* d_in, const int* in_sizes, int n_in,
                              void* d_out, int out_size) {
    const float* x        = (const float*)d_in[0];  // [4, 4096, 4096] f32
    const float* hadamard = (const float*)d_in[1];  // [16, 16] f32
    const float* signs    = (const float*)d_in[2];  // [16] f32
    float* out = (float*)d_out;

    long n_elems = (long)in_sizes[0];
    long n_vec = n_elems / 4;                       // float4 count

    had_prep_kernel<<<1, 256>>>(hadamard, signs);

    long per_block = 256L * VEC;
    int blocks_diag = (int)((n_vec + per_block - 1) / per_block);
    had_diag_kernel<<<blocks_diag, 256>>>((const float4*)x, (float4*)out, n_vec);

    int blocks_gen = (int)((n_vec + 255) / 256);
    had_general_kernel<<<blocks_gen, 256>>>((const float4*)x, (float4*)out, n_vec);
}

// round 4
// speedup vs baseline: 1.4499x; 1.4499x over previous
#include <cuda_runtime.h>
#include <cuda_bf16.h>

#define VEC 8

// One fused kernel. Each block:
//  1) rebuilds h_t[j][i] = hadamard[j][i] * signs[j] in shared (256 threads,
//     one element each), records the diagonal, and computes an "is diagonal"
//     flag with a single __syncthreads_or barrier.
//  2) diag path (this dataset): fully-coalesced grid-stride streaming scale.
//     Since stride % 4 == 0, the diag segment index (g & 3) == (t & 3) is
//     per-thread constant -> one shared read, then pure LDG/FMUL/STG.
//  3) general fallback: per-float4 gather of the 16-elem tile + 4x16 dot
//     products (correctness only; never taken for these inputs).
__global__ void __launch_bounds__(256)
had_fused_kernel(const float4* __restrict__ x, float4* __restrict__ out,
                 const float* __restrict__ hadamard,
                 const float* __restrict__ signs, long n_vec) {
    __shared__ float s_ht[256];
    __shared__ __align__(16) float s_diag[16];

    int t = threadIdx.x;
    int j = t >> 4;
    int i = t & 15;
    float v = hadamard[t] * signs[j];
    s_ht[t] = v;
    if (i == j) s_diag[j] = v;
    int offdiag = __syncthreads_or((i != j) && (v != 0.0f));

    long stride = (long)gridDim.x * 256;
    long g0 = (long)blockIdx.x * 256 + t;

    if (!offdiag) {
        // Diagonal fast path: elementwise scale, perfectly coalesced.
        float4 d = ((const float4*)s_diag)[t & 3];

        float4 val[VEC];
        long gi[VEC];
        // Front-batch all loads (MLP = VEC).
        #pragma unroll
        for (int k = 0; k < VEC; ++k) {
            gi[k] = g0 + (long)k * stride;
            if (gi[k] < n_vec) val[k] = __ldcs(&x[gi[k]]);
        }
        #pragma unroll
        for (int k = 0; k < VEC; ++k) {
            if (gi[k] < n_vec) {
                float4 r = make_float4(val[k].x * d.x, val[k].y * d.y,
                                       val[k].z * d.z, val[k].w * d.w);
                __stcs(&out[gi[k]], r);
            }
        }
    } else {
        // General fallback: thread owns output float4 g; its 16-elem input
        // tile starts at float4 index (g & ~3L). seg = g & 3 == t & 3.
        int seg = t & 3;
        for (int k = 0; k < VEC; ++k) {
            long g = g0 + (long)k * stride;
            if (g >= n_vec) continue;
            const float* xt = (const float*)(x + (g & ~3L));
            float xv[16];
            #pragma unroll
            for (int ii = 0; ii < 16; ++ii) xv[ii] = xt[ii];
            float o[4];
            #pragma unroll
            for (int jj = 0; jj < 4; ++jj) {
                int row = seg * 4 + jj;
                float acc = 0.0f;
                #pragma unroll
                for (int ii = 0; ii < 16; ++ii)
                    acc = fmaf(xv[ii], s_ht[row * 16 + ii], acc);
                o[jj] = acc;
            }
            out[g] = make_float4(o[0], o[1], o[2], o[3]);
        }
    }
}

extern "C" void kernel_launch(void* const* d_in, const int* in_sizes, int n_in,
                              void* d_out, int out_size) {
    const float* x        = (const float*)d_in[0];  // [4, 4096, 4096] f32
    const float* hadamard = (const float*)d_in[1];  // [16, 16] f32
    const float* signs    = (const float*)d_in[2];  // [16] f32
    float* out = (float*)d_out;

    long n_elems = (long)in_sizes[0];
    long n_vec = n_elems / 4;                       // float4 count

    long per_block = 256L * VEC;
    int blocks = (int)((n_vec + per_block - 1) / per_block);
    had_fused_kernel<<<blocks, 256>>>((const float4*)x, (float4*)out,
                                      hadamard, signs, n_vec);
}

// round 5
// speedup vs baseline: 1.4505x; 1.0004x over previous
#include <cuda_runtime.h>
#include <cuda_bf16.h>

#define VEC 8

// Single fused kernel. Each block rebuilds h_t = hadamard * signs[:,None] in
// shared, computes an "is diagonal" flag via __syncthreads_or, then takes a
// grid-uniform branch:
//  - diag path (this dataset): coalesced grid-stride streaming scale. Since
//    stride % 4 == 0, diag segment (g & 3) == (t & 3) is per-thread constant.
//    Two pipelined batches of 4 front-batched LDG.128s keep live registers
//    low (higher occupancy) while preserving MLP.
//  - general fallback: per-float4 gather of the 16-elem tile + 4x16 dots.
//    Never executes for these inputs; spills there are harmless.
__global__ void __launch_bounds__(256, 6)
had_fused_kernel(const float4* __restrict__ x, float4* __restrict__ out,
                 const float* __restrict__ hadamard,
                 const float* __restrict__ signs, unsigned n_vec) {
    __shared__ float s_ht[256];
    __shared__ __align__(16) float s_diag[16];

    int t = threadIdx.x;
    int j = t >> 4;
    int i = t & 15;
    float v = hadamard[t] * signs[j];
    s_ht[t] = v;
    if (i == j) s_diag[j] = v;
    int offdiag = __syncthreads_or((i != j) && (v != 0.0f));

    unsigned stride = gridDim.x * 256u;
    unsigned g0 = blockIdx.x * 256u + (unsigned)t;

    if (!offdiag) {
        float4 d = ((const float4*)s_diag)[t & 3];
        const float4* xp = x + g0;
        float4* op = out + g0;

        if (g0 + 7u * stride < n_vec) {
            // Full-range fast path: no per-access guards.
            float4 a0, a1, a2, a3;
            // Batch 1 (MLP = 4)
            a0 = __ldcs(xp + 0u * stride);
            a1 = __ldcs(xp + 1u * stride);
            a2 = __ldcs(xp + 2u * stride);
            a3 = __ldcs(xp + 3u * stride);
            __stcs(op + 0u * stride, make_float4(a0.x*d.x, a0.y*d.y, a0.z*d.z, a0.w*d.w));
            __stcs(op + 1u * stride, make_float4(a1.x*d.x, a1.y*d.y, a1.z*d.z, a1.w*d.w));
            __stcs(op + 2u * stride, make_float4(a2.x*d.x, a2.y*d.y, a2.z*d.z, a2.w*d.w));
            __stcs(op + 3u * stride, make_float4(a3.x*d.x, a3.y*d.y, a3.z*d.z, a3.w*d.w));
            // Batch 2 (MLP = 4)
            a0 = __ldcs(xp + 4u * stride);
            a1 = __ldcs(xp + 5u * stride);
            a2 = __ldcs(xp + 6u * stride);
            a3 = __ldcs(xp + 7u * stride);
            __stcs(op + 4u * stride, make_float4(a0.x*d.x, a0.y*d.y, a0.z*d.z, a0.w*d.w));
            __stcs(op + 5u * stride, make_float4(a1.x*d.x, a1.y*d.y, a1.z*d.z, a1.w*d.w));
            __stcs(op + 6u * stride, make_float4(a2.x*d.x, a2.y*d.y, a2.z*d.z, a2.w*d.w));
            __stcs(op + 7u * stride, make_float4(a3.x*d.x, a3.y*d.y, a3.z*d.z, a3.w*d.w));
        } else {
            // Tail blocks: guarded.
            #pragma unroll
            for (int k = 0; k < VEC; ++k) {
                unsigned g = g0 + (unsigned)k * stride;
                if (g < n_vec) {
                    float4 a = __ldcs(&x[g]);
                    __stcs(&out[g], make_float4(a.x*d.x, a.y*d.y, a.z*d.z, a.w*d.w));
                }
            }
        }
    } else {
        // General fallback (correctness only). seg = g & 3 == t & 3.
        int seg = t & 3;
        for (int k = 0; k < VEC; ++k) {
            unsigned g = g0 + (unsigned)k * stride;
            if (g >= n_vec) continue;
            const float* xt = (const float*)(x + (g & ~3u));
            float xv[16];
            #pragma unroll
            for (int ii = 0; ii < 16; ++ii) xv[ii] = xt[ii];
            float o[4];
            #pragma unroll
            for (int jj = 0; jj < 4; ++jj) {
                int row = seg * 4 + jj;
                float acc = 0.0f;
                #pragma unroll
                for (int ii = 0; ii < 16; ++ii)
                    acc = fmaf(xv[ii], s_ht[row * 16 + ii], acc);
                o[jj] = acc;
            }
            out[g] = make_float4(o[0], o[1], o[2], o[3]);
        }
    }
}

extern "C" void kernel_launch(void* const* d_in, const int* in_sizes, int n_in,
                              void* d_out, int out_size) {
    const float* x        = (const float*)d_in[0];  // [4, 4096, 4096] f32
    const float* hadamard = (const float*)d_in[1];  // [16, 16] f32
    const float* signs    = (const float*)d_in[2];  // [16] f32
    float* out = (float*)d_out;

    unsigned n_vec = (unsigned)(in_sizes[0] / 4);   // float4 count (fits: int input)

    unsigned per_block = 256u * VEC;
    int blocks = (int)((n_vec + per_block - 1) / per_block);
    had_fused_kernel<<<blocks, 256>>>((const float4*)x, (float4*)out,
                                      hadamard, signs, n_vec);
}